// round 7
// baseline (speedup 1.0000x reference)
#include <cuda_runtime.h>

// DynamicHead: per-sample grouped 1x1 conv (KERNEL_SIZE=1, PAD=0).
// f:      [B=8, C=400, H=128, W=128] fp32   (210 MB, read exactly once)
// kernel: [B=8, N=50, CPG=8, 1, 1]   fp32   (12.8 KB, L1-resident)
// out:    [B=8, N=50, H=128, W=128]  fp32   (26 MB, written once)
//
// FINAL (converged): pure HBM-bound at the measured DRAM-efficiency ceiling
// (~6.2 TB/s for this 89/11 read/write streaming mix). Verified insensitive
// to: CTA mapping (R2 vs R3), occupancy 63-96%, cache policy (.cs regressed
// -2.4%), access width (LDG.256 regressed -5%). Traffic is provably minimal
// (236 MB, zero reuse). Config below is the fastest measured:
//   grid-stride over flattened float4 output, one resident wave
//   (SMs x 8 CTAs x 256 thr), 8 independent LDG.128 per output (MLP=8),
//   default cache policy, warp-uniform L1-broadcast weights.

#define N_      50
#define HW4_    4096                      // 128*128/4 float4 per plane
#define TOTAL4  (8 * 50 * HW4_)           // 1,638,400 output float4
#define TPB_    256

__global__ __launch_bounds__(TPB_)
void dynhead_1x1_gs(const float4* __restrict__ f4,
                    const float* __restrict__ kern,
                    float4* __restrict__ o4) {
    const int stride = gridDim.x * TPB_;
    for (int idx = blockIdx.x * TPB_ + threadIdx.x; idx < TOTAL4; idx += stride) {
        const int bn  = idx >> 12;            // idx / 4096  (0..399)
        const int pos = idx & (HW4_ - 1);
        const int b = bn / N_;                // magic-mul division
        const int n = bn - b * N_;

        // 8 group weights: warp-uniform (whole warp shares bn), L1 broadcast.
        const float* kp = kern + bn * 8;
        float w0 = __ldg(kp + 0), w1 = __ldg(kp + 1);
        float w2 = __ldg(kp + 2), w3 = __ldg(kp + 3);
        float w4 = __ldg(kp + 4), w5 = __ldg(kp + 5);
        float w6 = __ldg(kp + 6), w7 = __ldg(kp + 7);

        // 8 input channel planes for this group; 8 independent LDG.128 (MLP=8).
        const float4* fp = f4 + (((b * 400 + n * 8) << 12) + pos);
        const float4 v0 = fp[0 * HW4_];
        const float4 v1 = fp[1 * HW4_];
        const float4 v2 = fp[2 * HW4_];
        const float4 v3 = fp[3 * HW4_];
        const float4 v4 = fp[4 * HW4_];
        const float4 v5 = fp[5 * HW4_];
        const float4 v6 = fp[6 * HW4_];
        const float4 v7 = fp[7 * HW4_];

        float4 acc;
        acc.x = v0.x * w0; acc.y = v0.y * w0; acc.z = v0.z * w0; acc.w = v0.w * w0;
        acc.x = fmaf(w1, v1.x, acc.x); acc.y = fmaf(w1, v1.y, acc.y);
        acc.z = fmaf(w1, v1.z, acc.z); acc.w = fmaf(w1, v1.w, acc.w);
        acc.x = fmaf(w2, v2.x, acc.x); acc.y = fmaf(w2, v2.y, acc.y);
        acc.z = fmaf(w2, v2.z, acc.z); acc.w = fmaf(w2, v2.w, acc.w);
        acc.x = fmaf(w3, v3.x, acc.x); acc.y = fmaf(w3, v3.y, acc.y);
        acc.z = fmaf(w3, v3.z, acc.z); acc.w = fmaf(w3, v3.w, acc.w);
        acc.x = fmaf(w4, v4.x, acc.x); acc.y = fmaf(w4, v4.y, acc.y);
        acc.z = fmaf(w4, v4.z, acc.z); acc.w = fmaf(w4, v4.w, acc.w);
        acc.x = fmaf(w5, v5.x, acc.x); acc.y = fmaf(w5, v5.y, acc.y);
        acc.z = fmaf(w5, v5.z, acc.z); acc.w = fmaf(w5, v5.w, acc.w);
        acc.x = fmaf(w6, v6.x, acc.x); acc.y = fmaf(w6, v6.y, acc.y);
        acc.z = fmaf(w6, v6.z, acc.z); acc.w = fmaf(w6, v6.w, acc.w);
        acc.x = fmaf(w7, v7.x, acc.x); acc.y = fmaf(w7, v7.y, acc.y);
        acc.z = fmaf(w7, v7.z, acc.z); acc.w = fmaf(w7, v7.w, acc.w);

        o4[idx] = acc;
    }
}

extern "C" void kernel_launch(void* const* d_in, const int* in_sizes, int n_in,
                              void* d_out, int out_size) {
    const float4* f4  = (const float4*)d_in[0];
    const float* kern = (const float*)d_in[1];
    float4* o4        = (float4*)d_out;

    // Exactly one resident wave: 8 CTAs/SM (256 thr -> 2048/SM cap).
    // Host-side attribute query runs at capture time only.
    int sm = 148;
    cudaDeviceGetAttribute(&sm, cudaDevAttrMultiProcessorCount, 0);
    dim3 grid(sm * 8);
    dynhead_1x1_gs<<<grid, TPB_>>>(f4, kern, o4);
}

// round 8
// speedup vs baseline: 1.0427x; 1.0427x over previous
#include <cuda_runtime.h>

// DynamicHead: per-sample grouped 1x1 conv (KERNEL_SIZE=1, PAD=0).
// f:      [B=8, C=400, H=128, W=128] fp32   (210 MB, read exactly once)
// kernel: [B=8, N=50, CPG=8]         fp32   (12.8 KB)
// out:    [B=8, N=50, H=128, W=128]  fp32   (26 MB, written once)
//
// R7: DRAM page-locality experiment. Previous mappings kept all 3200 input
// planes concurrently in flight (512B/warp granularity per stream). Here,
// 8 CTAs cooperate per (b,n) group: at any instant only ~1216 planes are
// active, each consumed in long contiguous bursts -> higher row-buffer hit
// rate at the memory controller. All SM-side structure (float4 LDG.128 x8,
// default policy, 256 thr, one resident wave) identical to proven-best.

#define N_      50
#define HW4_    4096                      // 128*128/4 float4 per plane
#define BN_     400
#define TPB_    256

__global__ __launch_bounds__(TPB_)
void dynhead_1x1_stripe(const float4* __restrict__ f4,
                        const float* __restrict__ kern,
                        float4* __restrict__ o4) {
    const int g       = blockIdx.x >> 3;        // group id
    const int sub     = blockIdx.x & 7;         // 0..7 within group
    const int ngroups = gridDim.x >> 3;

    for (int bn = g; bn < BN_; bn += ngroups) {
        const int b = bn / N_;
        const int n = bn - b * N_;

        // 8 group weights: warp-uniform, L1 broadcast.
        const float* kp = kern + bn * 8;
        const float w0 = __ldg(kp + 0), w1 = __ldg(kp + 1);
        const float w2 = __ldg(kp + 2), w3 = __ldg(kp + 3);
        const float w4 = __ldg(kp + 4), w5 = __ldg(kp + 5);
        const float w6 = __ldg(kp + 6), w7 = __ldg(kp + 7);

        const float4* __restrict__ fp = f4 + ((b * 400 + n * 8) << 12);
        float4* __restrict__ op = o4 + (bn << 12);

        // 8 sub-CTAs x 256 thr x 2 iters = 4096 float4 = one full plane set.
        // sub-CTA s owns contiguous pos range [s*512, (s+1)*512).
        int pos = sub * 512 + threadIdx.x;
#pragma unroll
        for (int i = 0; i < 2; i++, pos += TPB_) {
            const float4 v0 = fp[0 * HW4_ + pos];
            const float4 v1 = fp[1 * HW4_ + pos];
            const float4 v2 = fp[2 * HW4_ + pos];
            const float4 v3 = fp[3 * HW4_ + pos];
            const float4 v4 = fp[4 * HW4_ + pos];
            const float4 v5 = fp[5 * HW4_ + pos];
            const float4 v6 = fp[6 * HW4_ + pos];
            const float4 v7 = fp[7 * HW4_ + pos];

            float4 acc;
            acc.x = v0.x * w0; acc.y = v0.y * w0; acc.z = v0.z * w0; acc.w = v0.w * w0;
            acc.x = fmaf(w1, v1.x, acc.x); acc.y = fmaf(w1, v1.y, acc.y);
            acc.z = fmaf(w1, v1.z, acc.z); acc.w = fmaf(w1, v1.w, acc.w);
            acc.x = fmaf(w2, v2.x, acc.x); acc.y = fmaf(w2, v2.y, acc.y);
            acc.z = fmaf(w2, v2.z, acc.z); acc.w = fmaf(w2, v2.w, acc.w);
            acc.x = fmaf(w3, v3.x, acc.x); acc.y = fmaf(w3, v3.y, acc.y);
            acc.z = fmaf(w3, v3.z, acc.z); acc.w = fmaf(w3, v3.w, acc.w);
            acc.x = fmaf(w4, v4.x, acc.x); acc.y = fmaf(w4, v4.y, acc.y);
            acc.z = fmaf(w4, v4.z, acc.z); acc.w = fmaf(w4, v4.w, acc.w);
            acc.x = fmaf(w5, v5.x, acc.x); acc.y = fmaf(w5, v5.y, acc.y);
            acc.z = fmaf(w5, v5.z, acc.z); acc.w = fmaf(w5, v5.w, acc.w);
            acc.x = fmaf(w6, v6.x, acc.x); acc.y = fmaf(w6, v6.y, acc.y);
            acc.z = fmaf(w6, v6.z, acc.z); acc.w = fmaf(w6, v6.w, acc.w);
            acc.x = fmaf(w7, v7.x, acc.x); acc.y = fmaf(w7, v7.y, acc.y);
            acc.z = fmaf(w7, v7.z, acc.z); acc.w = fmaf(w7, v7.w, acc.w);

            op[pos] = acc;
        }
    }
}

extern "C" void kernel_launch(void* const* d_in, const int* in_sizes, int n_in,
                              void* d_out, int out_size) {
    const float4* f4  = (const float4*)d_in[0];
    const float* kern = (const float*)d_in[1];
    float4* o4        = (float4*)d_out;

    // One resident wave: 8 CTAs/SM; groups of 8 CTAs share one bn stripe.
    int sm = 148;
    cudaDeviceGetAttribute(&sm, cudaDevAttrMultiProcessorCount, 0);
    dim3 grid(sm * 8);
    dynhead_1x1_stripe<<<grid, TPB_>>>(f4, kern, o4);
}